// round 11
// baseline (speedup 1.0000x reference)
#include <cuda_runtime.h>
#include <math.h>
#include <stdint.h>

typedef unsigned long long ull;

#define SEQ   1024
#define BATCH 64
#define DIN   256
#define HID   512
#define BUN   512

// ---------------- device scratch (no allocation allowed) ----------------
// g_C layout: [t][g 8][j 512][r 8]  (g = batch/8, r = row-in-group)
__device__ __align__(16) float g_C[(size_t)SEQ * 8 * 512 * 8];    // 128 MB
__device__ __align__(16) float g_H2[2][8 * 4096];                 // h double buffer [par][g][j][r]
__device__ __align__(16) float g_P[768 * 512];                    // P = Wb @ Wh
__device__ __align__(16) float g_c0[512];                         // bb@Wh + bh
__device__ unsigned g_flag[4096];                                 // per (g,cb) step flag, 128B apart

// ---------------- packed f32x2 helpers ----------------
__device__ __forceinline__ ull ffma2(ull a, ull b, ull c) {
    ull d; asm("fma.rn.f32x2 %0, %1, %2, %3;" : "=l"(d) : "l"(a), "l"(b), "l"(c)); return d;
}
__device__ __forceinline__ ull add2(ull a, ull b) {
    ull d; asm("add.rn.f32x2 %0, %1, %2;" : "=l"(d) : "l"(a), "l"(b)); return d;
}
__device__ __forceinline__ ull pack2(float x, float y) {
    ull d; asm("mov.b64 %0, {%1, %2};" : "=l"(d) : "f"(x), "f"(y)); return d;
}
__device__ __forceinline__ float2 unpack2(ull a) {
    float2 r; asm("mov.b64 {%0, %1}, %2;" : "=f"(r.x), "=f"(r.y) : "l"(a)); return r;
}

// ---------------- L1-bypassing global access ----------------
__device__ __forceinline__ float4 ldcg4(const float* p) {
    float4 v;
    asm volatile("ld.global.cg.v4.f32 {%0,%1,%2,%3}, [%4];"
                 : "=f"(v.x), "=f"(v.y), "=f"(v.z), "=f"(v.w) : "l"(p));
    return v;
}
__device__ __forceinline__ ull ldcg8(const float* p) {
    ull v; asm volatile("ld.global.cg.u64 %0, [%1];" : "=l"(v) : "l"(p)); return v;
}
__device__ __forceinline__ void stcg8(float* p, ull v) {
    asm volatile("st.global.cg.u64 [%0], %1;" :: "l"(p), "l"(v));
}

// ---------------- init: zero h buf0 and flags (every replay) ------
__global__ void __launch_bounds__(256) init_kernel() {
    int t = threadIdx.x;
    for (int i = t; i < 4096; i += 256) g_flag[i] = 0u;
    for (int i = t; i < 8 * 4096; i += 256) g_H2[0][i] = 0.0f;
}

// ---------------------------------------------------------------------------
// c0[u] = sum_j bb[j] * Wh[j][u] + bh[u]
// ---------------------------------------------------------------------------
__global__ void __launch_bounds__(512) c0_kernel(const float* __restrict__ bb,
                                                 const float* __restrict__ Wh,
                                                 const float* __restrict__ bh) {
    int u = threadIdx.x;
    float s = __ldg(&bh[u]);
#pragma unroll 8
    for (int j = 0; j < BUN; j++)
        s += __ldg(&bb[j]) * __ldg(&Wh[(size_t)j * HID + u]);
    g_c0[u] = s;
}

// ---------------------------------------------------------------------------
// P = Wb @ Wh   (768 x 512, K = 512). grid (8 colblk, 12 rowblk), 256 thr.
// ---------------------------------------------------------------------------
__global__ void __launch_bounds__(256) pmat_kernel(const float* __restrict__ Wb,
                                                   const float* __restrict__ Wh) {
    __shared__ float Asm[64 * 32];   // [r][k]
    __shared__ float Bsm[32 * 64];   // [k][j]
    const int tid = threadIdx.x;
    const int tx  = tid & 15;
    const int ty  = tid >> 4;
    const int jb  = blockIdx.x * 64;
    const int rb  = blockIdx.y * 64;

    float acc[16];
#pragma unroll
    for (int i = 0; i < 16; i++) acc[i] = 0.0f;

    for (int kt = 0; kt < 16; kt++) {
        const int kg = kt * 32;
#pragma unroll
        for (int i = 0; i < 2; i++) {
            int v = tid + 256 * i;
            int r = v >> 3, q = v & 7;
            *(float4*)&Asm[r * 32 + 4 * q] =
                __ldg((const float4*)&Wb[(size_t)(rb + r) * BUN + kg + 4 * q]);
        }
#pragma unroll
        for (int i = 0; i < 2; i++) {
            int v = tid + 256 * i;
            int kk = v >> 4, q = v & 15;
            *(float4*)&Bsm[kk * 64 + 4 * q] =
                __ldg((const float4*)&Wh[(size_t)(kg + kk) * HID + jb + 4 * q]);
        }
        __syncthreads();
#pragma unroll 8
        for (int kk = 0; kk < 32; kk++) {
            float4 b = *(const float4*)&Bsm[kk * 64 + 4 * tx];
            float a0 = Asm[(4 * ty + 0) * 32 + kk];
            float a1 = Asm[(4 * ty + 1) * 32 + kk];
            float a2 = Asm[(4 * ty + 2) * 32 + kk];
            float a3 = Asm[(4 * ty + 3) * 32 + kk];
            acc[0]  += a0 * b.x; acc[1]  += a0 * b.y; acc[2]  += a0 * b.z; acc[3]  += a0 * b.w;
            acc[4]  += a1 * b.x; acc[5]  += a1 * b.y; acc[6]  += a1 * b.z; acc[7]  += a1 * b.w;
            acc[8]  += a2 * b.x; acc[9]  += a2 * b.y; acc[10] += a2 * b.z; acc[11] += a2 * b.w;
            acc[12] += a3 * b.x; acc[13] += a3 * b.y; acc[14] += a3 * b.z; acc[15] += a3 * b.w;
        }
        __syncthreads();
    }
#pragma unroll
    for (int i = 0; i < 4; i++) {
        float4 o = make_float4(acc[4 * i], acc[4 * i + 1], acc[4 * i + 2], acc[4 * i + 3]);
        *(float4*)&g_P[(size_t)(rb + 4 * ty + i) * 512 + jb + 4 * tx] = o;
    }
}

// ---------------------------------------------------------------------------
// Precompute C (R9-proven). grid (2 col-blocks, 1024 seq), 256 threads.
// ---------------------------------------------------------------------------
__global__ void __launch_bounds__(256) pre_kernel(const float* __restrict__ X) {
    __shared__ float AsmT[32 * 64];    // [k][b]  8 KB
    __shared__ float Bsm[32 * 256];    // [k][j]  32 KB

    const int tid = threadIdx.x;
    const int tx  = tid & 31;          // lane: col groups 4tx and 128+4tx
    const int ty  = tid >> 5;          // warp: rows 8ty..8ty+7 (one batch group)
    const int s   = blockIdx.y;
    const int jb  = blockIdx.x * 256;

    ull acc[32];                        // [rowpair 4][col 8]
#pragma unroll
    for (int i = 0; i < 32; i++) acc[i] = 0ull;

    for (int kt = 0; kt < 8; kt++) {
        const int kg = kt * 32;
#pragma unroll
        for (int i = 0; i < 2; i++) {
            int v = tid + 256 * i;      // 0..511 float4-slots
            int b = v >> 3, q = v & 7;
            float4 a = __ldg((const float4*)&X[(size_t)b * (SEQ * DIN) + (size_t)s * DIN + kg + 4 * q]);
            AsmT[(4 * q + 0) * 64 + b] = a.x;
            AsmT[(4 * q + 1) * 64 + b] = a.y;
            AsmT[(4 * q + 2) * 64 + b] = a.z;
            AsmT[(4 * q + 3) * 64 + b] = a.w;
        }
#pragma unroll
        for (int i = 0; i < 8; i++) {
            int v = tid + 256 * i;      // 0..2047 float4-slots
            int k = v >> 6, q = v & 63;
            *(float4*)&Bsm[k * 256 + 4 * q] =
                *(const float4*)&g_P[(size_t)(kg + k) * 512 + jb + 4 * q];
        }
        __syncthreads();
#pragma unroll 8
        for (int k = 0; k < 32; k++) {
            float4 wA = *(const float4*)&Bsm[k * 256 + 4 * tx];
            float4 wB = *(const float4*)&Bsm[k * 256 + 128 + 4 * tx];
            ulonglong2 aA = *(const ulonglong2*)&AsmT[k * 64 + 8 * ty];
            ulonglong2 aB = *(const ulonglong2*)&AsmT[k * 64 + 8 * ty + 4];
            ull w0 = pack2(wA.x, wA.x), w1 = pack2(wA.y, wA.y);
            ull w2 = pack2(wA.z, wA.z), w3 = pack2(wA.w, wA.w);
            ull w4 = pack2(wB.x, wB.x), w5 = pack2(wB.y, wB.y);
            ull w6 = pack2(wB.z, wB.z), w7 = pack2(wB.w, wB.w);
            acc[0]  = ffma2(aA.x, w0, acc[0]);
            acc[1]  = ffma2(aA.x, w1, acc[1]);
            acc[2]  = ffma2(aA.x, w2, acc[2]);
            acc[3]  = ffma2(aA.x, w3, acc[3]);
            acc[4]  = ffma2(aA.x, w4, acc[4]);
            acc[5]  = ffma2(aA.x, w5, acc[5]);
            acc[6]  = ffma2(aA.x, w6, acc[6]);
            acc[7]  = ffma2(aA.x, w7, acc[7]);
            acc[8]  = ffma2(aA.y, w0, acc[8]);
            acc[9]  = ffma2(aA.y, w1, acc[9]);
            acc[10] = ffma2(aA.y, w2, acc[10]);
            acc[11] = ffma2(aA.y, w3, acc[11]);
            acc[12] = ffma2(aA.y, w4, acc[12]);
            acc[13] = ffma2(aA.y, w5, acc[13]);
            acc[14] = ffma2(aA.y, w6, acc[14]);
            acc[15] = ffma2(aA.y, w7, acc[15]);
            acc[16] = ffma2(aB.x, w0, acc[16]);
            acc[17] = ffma2(aB.x, w1, acc[17]);
            acc[18] = ffma2(aB.x, w2, acc[18]);
            acc[19] = ffma2(aB.x, w3, acc[19]);
            acc[20] = ffma2(aB.x, w4, acc[20]);
            acc[21] = ffma2(aB.x, w5, acc[21]);
            acc[22] = ffma2(aB.x, w6, acc[22]);
            acc[23] = ffma2(aB.x, w7, acc[23]);
            acc[24] = ffma2(aB.y, w0, acc[24]);
            acc[25] = ffma2(aB.y, w1, acc[25]);
            acc[26] = ffma2(aB.y, w2, acc[26]);
            acc[27] = ffma2(aB.y, w3, acc[27]);
            acc[28] = ffma2(aB.y, w4, acc[28]);
            acc[29] = ffma2(aB.y, w5, acc[29]);
            acc[30] = ffma2(aB.y, w6, acc[30]);
            acc[31] = ffma2(aB.y, w7, acc[31]);
        }
        __syncthreads();
    }

    float4 bias0 = *(const float4*)&g_c0[jb + 4 * tx];
    float4 bias1 = *(const float4*)&g_c0[jb + 128 + 4 * tx];
    float bias[8] = {bias0.x, bias0.y, bias0.z, bias0.w,
                     bias1.x, bias1.y, bias1.z, bias1.w};
#pragma unroll
    for (int c = 0; c < 8; c++) {
        int j = jb + ((c < 4) ? (4 * tx + c) : (128 + 4 * tx + c - 4));
        float bv = bias[c];
        float2 u0 = unpack2(acc[0 * 8 + c]);
        float2 u1 = unpack2(acc[1 * 8 + c]);
        float2 u2 = unpack2(acc[2 * 8 + c]);
        float2 u3 = unpack2(acc[3 * 8 + c]);
        float4 lo = make_float4(u0.x + bv, u0.y + bv, u1.x + bv, u1.y + bv);
        float4 hi = make_float4(u2.x + bv, u2.y + bv, u3.x + bv, u3.y + bv);
        float* dst = &g_C[(((size_t)s * 8 + ty) * 512 + j) * 8];
        *(float4*)dst = lo;
        *(float4*)(dst + 4) = hi;
    }
}

// ---------------------------------------------------------------------------
// Persistent recurrent kernel: 128 CTAs = 8 groups x 16 col-blocks.
// Dataflow sync: per-producer step flags; consumer warp w needs only
// producers 2w, 2w+1. h double-buffered by parity; RED double-buffered.
// ---------------------------------------------------------------------------
#define HT_F   4352                  // floats (32 slices x 136)
#define RED_U  4160                  // ulls per parity buffer (32 x 130)
#define RECSM  (HT_F * 4 + 2 * RED_U * 8)   // 83968 bytes

__global__ void __launch_bounds__(256, 1) rec_kernel(const float* __restrict__ tau,
                                                     float* __restrict__ out) {
    extern __shared__ float smem[];
    float* HT   = smem;                       // warp-private staged h slices
    ull*   REDB = (ull*)(smem + HT_F);        // 2 parity buffers

    const int tid  = threadIdx.x;
    const int lane = tid & 31;
    const int w    = tid >> 5;
    const int g    = blockIdx.x >> 4;    // batch group
    const int cb   = blockIdx.x & 15;    // column block
    const int j0   = cb * 32;
    const int cg   = tid & 7;            // column sub-group (4 cols)
    const int ks   = tid >> 3;           // k-slice 0..31 (16 k each)
    const int c0   = 4 * cg;

    // --- weights into registers: 16 x float4, held for all 1024 steps ---
    float4 wf[16];
    {
        const float* ws = &g_P[(size_t)(256 + 16 * ks) * 512 + j0 + c0];
#pragma unroll
        for (int i = 0; i < 16; i++)
            wf[i] = __ldg((const float4*)(ws + (size_t)i * 512));
    }

    // --- epilogue state (tid < 128) ---
    float ertau = 0.0f;
    ull h_reg = 0ull, cv = 0ull;
    const float* cpp = g_C;
    float *o0 = out, *o1 = out, *gh0 = g_H2[0], *gh1 = g_H2[1];
    unsigned* fown = &g_flag[(g * 16 + cb) * 32];
    if (tid < 128) {
        int erp = tid >> 5;             // row pair (rows 2erp, 2erp+1)
        int ec = tid & 31;
        int ej = j0 + ec;
        ertau = 1.0f / __ldg(&tau[ej]);
        cpp = g_C + ((size_t)g * 512 + ej) * 8 + 2 * erp;
        int b0 = g * 8 + 2 * erp;
        o0 = out + ((size_t)b0 * SEQ) * HID + ej;
        o1 = out + ((size_t)(b0 + 1) * SEQ) * HID + ej;
        gh0 = &g_H2[0][g * 4096 + ej * 8 + 2 * erp];
        gh1 = &g_H2[1][g * 4096 + ej * 8 + 2 * erp];
        cv = ldcg8(cpp);                // C for t = 0
    }

    // consumer-side: half-warp hw handles producer 2w+hw's 256-float chunk
    const int hw = lane >> 4;
    const int ll = lane & 15;
    const unsigned* fsrc = &g_flag[(g * 16 + 2 * w + hw) * 32];
    const float* hb0 = &g_H2[0][g * 4096 + 512 * w + 256 * hw];
    const float* hb1 = &g_H2[1][g * 4096 + 512 * w + 256 * hw];
    float* HTw = HT + 4 * w * 136;
    const float* ht_p = HT + ks * 136;

    for (int t = 0; t < SEQ; t++) {
        // ---- wait for my producer's h_t (per-lane acquire) ----
        {
            unsigned v;
            do {
                asm volatile("ld.acquire.gpu.global.u32 %0, [%1];" : "=r"(v) : "l"(fsrc) : "memory");
            } while ((int)v < t);
        }
        // ---- stage this half-warp's 256-float chunk into warp-private HT ----
        {
            const float* hb = (t & 1) ? hb1 : hb0;
#pragma unroll
            for (int i = 0; i < 4; i++) {
                int s4 = ll + 16 * i;           // float4 slot 0..63 within chunk
                float4 d = ldcg4(hb + 4 * s4);
                int kl = 32 * hw + (s4 >> 1);   // local k 0..63
                int half = s4 & 1;
                *(float4*)&HTw[(kl >> 4) * 136 + (kl & 15) * 8 + 4 * half] = d;
            }
        }
        __syncwarp();

        // ---- kloop: 16 k, weights from registers, h broadcast from smem ----
        ull acc[16];
#pragma unroll
        for (int i = 0; i < 16; i++) acc[i] = 0ull;
#pragma unroll
        for (int i = 0; i < 16; i++) {
            ulonglong2 hA = *(const ulonglong2*)(ht_p + 8 * i);
            ulonglong2 hB = *(const ulonglong2*)(ht_p + 8 * i + 4);
            float4 wv = wf[i];
            ull w0 = pack2(wv.x, wv.x), w1 = pack2(wv.y, wv.y);
            ull w2 = pack2(wv.z, wv.z), w3 = pack2(wv.w, wv.w);
            acc[0]  = ffma2(hA.x, w0, acc[0]);
            acc[1]  = ffma2(hA.x, w1, acc[1]);
            acc[2]  = ffma2(hA.x, w2, acc[2]);
            acc[3]  = ffma2(hA.x, w3, acc[3]);
            acc[4]  = ffma2(hA.y, w0, acc[4]);
            acc[5]  = ffma2(hA.y, w1, acc[5]);
            acc[6]  = ffma2(hA.y, w2, acc[6]);
            acc[7]  = ffma2(hA.y, w3, acc[7]);
            acc[8]  = ffma2(hB.x, w0, acc[8]);
            acc[9]  = ffma2(hB.x, w1, acc[9]);
            acc[10] = ffma2(hB.x, w2, acc[10]);
            acc[11] = ffma2(hB.x, w3, acc[11]);
            acc[12] = ffma2(hB.y, w0, acc[12]);
            acc[13] = ffma2(hB.y, w1, acc[13]);
            acc[14] = ffma2(hB.y, w2, acc[14]);
            acc[15] = ffma2(hB.y, w3, acc[15]);
        }
        // ---- write partials to this step's parity RED buffer ----
        {
            ull* RED = REDB + (t & 1) * RED_U;
#pragma unroll
            for (int rp = 0; rp < 4; rp++) {
                ulonglong2 v0, v1;
                v0.x = acc[rp * 4 + 0]; v0.y = acc[rp * 4 + 1];
                v1.x = acc[rp * 4 + 2]; v1.y = acc[rp * 4 + 3];
                *(ulonglong2*)&RED[ks * 130 + rp * 32 + c0]     = v0;
                *(ulonglong2*)&RED[ks * 130 + rp * 32 + c0 + 2] = v1;
            }
        }
        __syncthreads();                 // all warps' partials visible to reducers

        if (tid < 128) {
            const ull* rb = REDB + (t & 1) * RED_U + tid;
            ull s0 = rb[0];
            ull s1 = rb[130];
            ull s2 = rb[2 * 130];
            ull s3 = rb[3 * 130];
#pragma unroll
            for (int i = 4; i < 32; i += 4) {
                s0 = add2(s0, rb[(i + 0) * 130]);
                s1 = add2(s1, rb[(i + 1) * 130]);
                s2 = add2(s2, rb[(i + 2) * 130]);
                s3 = add2(s3, rb[(i + 3) * 130]);
            }
            float2 z = unpack2(add2(add2(s0, s1), add2(s2, s3)));
            float2 c = unpack2(cv);
            float d0 = tanhf(z.x + c.x);
            float d1 = tanhf(z.y + c.y);
            float2 h = unpack2(h_reg);
            float hn0 = h.x + (d0 - h.x) * ertau;
            float hn1 = h.y + (d1 - h.y) * ertau;
            h_reg = pack2(hn0, hn1);
            // h_{t+1} goes to parity (t+1)&1
            stcg8((t & 1) ? gh0 : gh1, h_reg);
            o0[(size_t)t * HID] = hn0;
            o1[(size_t)t * HID] = hn1;
            if (t + 1 < SEQ) { cpp += 8 * 4096; cv = ldcg8(cpp); }
            __threadfence();             // release h stores (gpu scope)
            asm volatile("bar.sync 1, 128;" ::: "memory");
            if (tid == 0)
                asm volatile("st.release.gpu.global.u32 [%0], %1;"
                             :: "l"(fown), "r"((unsigned)(t + 1)) : "memory");
        }
        // non-epilogue warps run ahead to t+1: their flag polls gate them,
        // and RED/HT parity buffers make the one-step overlap race-free.
    }
}

// ---------------------------------------------------------------------------
extern "C" void kernel_launch(void* const* d_in, const int* in_sizes, int n_in,
                              void* d_out, int out_size) {
    (void)in_sizes; (void)n_in; (void)out_size;
    const float* X   = (const float*)d_in[0];
    const float* Wb  = (const float*)d_in[1];
    const float* bb  = (const float*)d_in[2];
    const float* Wh  = (const float*)d_in[3];
    const float* bh  = (const float*)d_in[4];
    const float* tau = (const float*)d_in[5];
    float* out = (float*)d_out;

    cudaFuncSetAttribute(rec_kernel, cudaFuncAttributeMaxDynamicSharedMemorySize, RECSM);

    init_kernel<<<1, 256>>>();
    c0_kernel<<<1, 512>>>(bb, Wh, bh);
    dim3 pgrid(8, 12);
    pmat_kernel<<<pgrid, 256>>>(Wb, Wh);
    dim3 cgrid(2, SEQ);
    pre_kernel<<<cgrid, 256>>>(X);
    rec_kernel<<<128, 256, RECSM>>>(tau, out);
}